// round 1
// baseline (speedup 1.0000x reference)
#include <cuda_runtime.h>

// Shapes: (64, 4, 256, 256) f32. Per-batch element count:
#define B 64
#define PER_BATCH (4 * 256 * 256)   // 262144
#define MARGIN 1.0f
#define NUM_PAIRS (B * (B - 1) / 2) // 2016

// Per-batch accumulators (device globals: no allocation allowed in kernel_launch)
__device__ float g_err[B];
__device__ float g_unc[B];

__global__ void zero_kernel() {
    int t = threadIdx.x;
    if (t < B) { g_err[t] = 0.0f; g_unc[t] = 0.0f; }
}

// 256 threads/block, each thread handles 4 float4 = 16 elems per tensor.
// elems per block = 256*16 = 4096 -> 64 chunks per batch -> grid = 64*64 = 4096 blocks.
#define THREADS 256
#define VEC_PER_THREAD 4           // float4s per thread per tensor
#define ELEMS_PER_BLOCK (THREADS * VEC_PER_THREAD * 4)  // 4096
#define CHUNKS_PER_BATCH (PER_BATCH / ELEMS_PER_BLOCK)  // 64

__global__ __launch_bounds__(THREADS)
void reduce_kernel(const float* __restrict__ pm,
                   const float* __restrict__ ps,
                   const float* __restrict__ tg) {
    int batch = blockIdx.x / CHUNKS_PER_BATCH;
    int chunk = blockIdx.x % CHUNKS_PER_BATCH;
    size_t base = (size_t)batch * PER_BATCH + (size_t)chunk * ELEMS_PER_BLOCK;

    const float4* pm4 = (const float4*)(pm + base);
    const float4* ps4 = (const float4*)(ps + base);
    const float4* tg4 = (const float4*)(tg + base);

    float e_sum = 0.0f, u_sum = 0.0f;

    #pragma unroll
    for (int i = 0; i < VEC_PER_THREAD; i++) {
        int idx = threadIdx.x + i * THREADS;  // coalesced: consecutive lanes adjacent
        float4 a = pm4[idx];
        float4 t = tg4[idx];
        float4 s = ps4[idx];
        e_sum += fabsf(a.x - t.x) + fabsf(a.y - t.y)
               + fabsf(a.z - t.z) + fabsf(a.w - t.w);
        u_sum += s.x + s.y + s.z + s.w;
    }

    // warp reduce
    #pragma unroll
    for (int off = 16; off > 0; off >>= 1) {
        e_sum += __shfl_down_sync(0xFFFFFFFFu, e_sum, off);
        u_sum += __shfl_down_sync(0xFFFFFFFFu, u_sum, off);
    }

    __shared__ float se[THREADS / 32], su[THREADS / 32];
    int lane = threadIdx.x & 31;
    int wid  = threadIdx.x >> 5;
    if (lane == 0) { se[wid] = e_sum; su[wid] = u_sum; }
    __syncthreads();

    if (wid == 0) {
        e_sum = (lane < THREADS / 32) ? se[lane] : 0.0f;
        u_sum = (lane < THREADS / 32) ? su[lane] : 0.0f;
        #pragma unroll
        for (int off = 4; off > 0; off >>= 1) {
            e_sum += __shfl_down_sync(0xFFFFFFFFu, e_sum, off);
            u_sum += __shfl_down_sync(0xFFFFFFFFu, u_sum, off);
        }
        if (lane == 0) {
            atomicAdd(&g_err[batch], e_sum);
            atomicAdd(&g_unc[batch], u_sum);
        }
    }
}

__global__ void finalize_kernel(float* __restrict__ out) {
    __shared__ float err_s[B], unc_s[B];
    int i = threadIdx.x;  // 64 threads
    const float inv_n = 1.0f / (float)PER_BATCH;
    err_s[i] = g_err[i] * inv_n;
    unc_s[i] = g_unc[i] * inv_n;
    __syncthreads();

    float ei = err_s[i], ui = unc_s[i];
    float sum = 0.0f;
    for (int j = i + 1; j < B; j++) {
        float ej = err_s[j], uj = unc_s[j];
        float d = (ei > ej) ? (uj - ui) : (ui - uj);
        sum += fmaxf(d + MARGIN, 0.0f);
    }

    // reduce 64 partial sums (2 warps)
    #pragma unroll
    for (int off = 16; off > 0; off >>= 1)
        sum += __shfl_down_sync(0xFFFFFFFFu, sum, off);

    __shared__ float ws[2];
    int lane = i & 31, wid = i >> 5;
    if (lane == 0) ws[wid] = sum;
    __syncthreads();
    if (i == 0) out[0] = (ws[0] + ws[1]) / (float)NUM_PAIRS;
}

extern "C" void kernel_launch(void* const* d_in, const int* in_sizes, int n_in,
                              void* d_out, int out_size) {
    const float* pred_mean = (const float*)d_in[0];
    const float* pred_std  = (const float*)d_in[1];
    const float* targets   = (const float*)d_in[2];
    float* out = (float*)d_out;

    zero_kernel<<<1, 64>>>();
    reduce_kernel<<<B * CHUNKS_PER_BATCH, THREADS>>>(pred_mean, pred_std, targets);
    finalize_kernel<<<1, B>>>(out);
}